// round 10
// baseline (speedup 1.0000x reference)
#include <cuda_runtime.h>

// image [1,128,128,512] f32 NHWC, RoI [N,4] f32 (cx,cy,w,h), POOL=7, STRIDE=16.
#define POOL    7
#define HH      128
#define WW      128
#define CC      512
#define NMAX    1024
#define MAXCELL (NMAX * POOL * POOL)
#define WARPS_PER_CTA 8

// Per-cell params (allocation-free rule: __device__ globals).
__device__ int4   g_off[MAXCELL];   // 4 corner offsets, float4 units
__device__ float4 g_w  [MAXCELL];   // 4 bilinear weights

// ---------------------------------------------------------------------------
// Kernel 1: one thread per (roi, py, px) cell -> corner offsets + weights.
// Matches reference math exactly (rintf = round-half-even, floor, clip order).
// ---------------------------------------------------------------------------
__global__ void roi_prep_kernel(const float* __restrict__ roi, int totalCells)
{
    int cell = blockIdx.x * blockDim.x + threadIdx.x;
    if (cell >= totalCells) return;

    int n   = cell / (POOL * POOL);
    int rem = cell - n * (POOL * POOL);
    int py  = rem / POOL;
    int px  = rem - py * POOL;

    const float inv_stride = 1.0f / 16.0f;
    float cx = roi[n * 4 + 0];
    float cy = roi[n * 4 + 1];
    float w  = roi[n * 4 + 2];
    float h  = roi[n * 4 + 3];

    float r  = rintf((cx - 0.5f * w) * inv_stride);   // x start (col)
    float c  = rintf((cy - 0.5f * h) * inv_stride);   // y start (row)
    float wq = fmaxf(rintf(w * inv_stride), 1.0f);
    float hq = fmaxf(rintf(h * inv_stride), 1.0f);

    // y axis (rows, limit HH)
    float gy  = (py + 0.5f) / (float)POOL;
    float sy  = fminf(fmaxf(gy * hq - 0.5f, 0.0f), hq - 1.0f);
    float fy0 = floorf(sy);
    float ly  = sy - fy0;
    float fy1 = fminf(fy0 + 1.0f, hq - 1.0f);
    int iy0 = (int)fminf(fmaxf(c + fy0, 0.0f), (float)(HH - 1));
    int iy1 = (int)fminf(fmaxf(c + fy1, 0.0f), (float)(HH - 1));

    // x axis (cols, limit WW)
    float gx  = (px + 0.5f) / (float)POOL;
    float sx  = fminf(fmaxf(gx * wq - 0.5f, 0.0f), wq - 1.0f);
    float fx0 = floorf(sx);
    float lx  = sx - fx0;
    float fx1 = fminf(fx0 + 1.0f, wq - 1.0f);
    int ix0 = (int)fminf(fmaxf(r + fx0, 0.0f), (float)(WW - 1));
    int ix1 = (int)fminf(fmaxf(r + fx1, 0.0f), (float)(WW - 1));

    g_off[cell] = make_int4((iy0 * WW + ix0) * (CC / 4),
                            (iy0 * WW + ix1) * (CC / 4),
                            (iy1 * WW + ix0) * (CC / 4),
                            (iy1 * WW + ix1) * (CC / 4));
    g_w[cell] = make_float4((1.0f - ly) * (1.0f - lx),
                            (1.0f - ly) * lx,
                            ly * (1.0f - lx),
                            ly * lx);
}

// ---------------------------------------------------------------------------
// Kernel 2: PERSISTENT, warp-per-cell, TMA-bulk stores.
// Each warp owns a cell: 32 lanes x 4 float4 chunks x 4 corners (LDG.128),
// blend, STS.128 into a per-warp double-buffered 2KB smem tile, then one
// lane issues cp.async.bulk (smem -> global, 2KB) on the async pipe.
// This removes the STG.128 issue cost (12 cyc/inst, ~40% of the LSU budget)
// from the LSU, which round-9 ncu showed to be the binding pipe (L1=74%).
// Warp-scope sync only: no CTA barriers, warps retire independently.
// ---------------------------------------------------------------------------
__global__ __launch_bounds__(256, 5)
void roi_pool_kernel(const float* __restrict__ img, float* __restrict__ out,
                     int totalCells)
{
    __shared__ float4 sbuf[WARPS_PER_CTA][2][CC / 4];   // 8 x 2 x 2KB = 32KB

    const int lane = threadIdx.x & 31;
    const int wid  = threadIdx.x >> 5;
    const int gwarp  = blockIdx.x * WARPS_PER_CTA + wid;
    const int nwarps = gridDim.x * WARPS_PER_CTA;

    const float4* __restrict__ img4 = (const float4*)img;

    int cell = gwarp;
    if (cell >= totalCells) return;

    // Prime: params for first cell (uniform across warp -> broadcast load).
    int4   o  = g_off[cell];
    float4 wt = g_w[cell];

    int it = 0;
    while (true) {
        int next = cell + nwarps;

        // Prefetch next cell's params (independent of this cell's data).
        int4   o_n  = o;
        float4 wt_n = wt;
        if (next < totalCells) {
            o_n  = g_off[next];
            wt_n = g_w[next];
        }

        float4* buf = &sbuf[wid][it & 1][0];

        // Ensure the bulk store that read this buffer two iterations ago has
        // finished reading it (allow 1 group pending = the other buffer's).
        if (it >= 2) {
            if (lane == 0)
                asm volatile("cp.async.bulk.wait_group.read 1;" ::: "memory");
            __syncwarp();
        }

        // 4 chunks x 4 corners; blend into registers, stage via STS.128.
        #pragma unroll
        for (int ch = 0; ch < 4; ++ch) {
            int idx = ch * 32 + lane;
            float4 a = __ldg(img4 + o.x + idx);
            float4 b = __ldg(img4 + o.y + idx);
            float4 c = __ldg(img4 + o.z + idx);
            float4 d = __ldg(img4 + o.w + idx);

            float4 r;
            r.x = wt.x * a.x + wt.y * b.x + wt.z * c.x + wt.w * d.x;
            r.y = wt.x * a.y + wt.y * b.y + wt.z * c.y + wt.w * d.y;
            r.z = wt.x * a.z + wt.y * b.z + wt.z * c.z + wt.w * d.z;
            r.w = wt.x * a.w + wt.y * b.w + wt.z * c.w + wt.w * d.w;

            buf[idx] = r;
        }

        __syncwarp();
        asm volatile("fence.proxy.async.shared::cta;" ::: "memory");

        if (lane == 0) {
            float* gdst = out + (size_t)cell * CC;
            unsigned saddr = (unsigned)__cvta_generic_to_shared(buf);
            asm volatile(
                "cp.async.bulk.global.shared::cta.bulk_group [%0], [%1], %2;"
                :: "l"(gdst), "r"(saddr), "n"(CC * 4) : "memory");
            asm volatile("cp.async.bulk.commit_group;" ::: "memory");
        }

        if (next >= totalCells) break;
        cell = next;
        o  = o_n;
        wt = wt_n;
        ++it;
    }

    // Kernel completion flushes pending bulk groups; explicit drain is cheap
    // insurance for smem lifetime.
    if (lane == 0)
        asm volatile("cp.async.bulk.wait_group.read 0;" ::: "memory");
}

extern "C" void kernel_launch(void* const* d_in, const int* in_sizes, int n_in,
                              void* d_out, int out_size)
{
    const float* img = (const float*)d_in[0];   // [1,128,128,512] f32
    const float* roi = (const float*)d_in[1];   // [N,4] f32
    float*       out = (float*)d_out;           // [1,N,7,7,512] f32

    int N = in_sizes[1] / 4;
    if (N > NMAX) N = NMAX;
    int totalCells = N * POOL * POOL;

    roi_prep_kernel<<<(totalCells + 255) / 256, 256>>>(roi, totalCells);

    int grid = 148 * 5;                           // one persistent wave
    int maxCtas = (totalCells + WARPS_PER_CTA - 1) / WARPS_PER_CTA;
    if (grid > maxCtas) grid = maxCtas;
    roi_pool_kernel<<<grid, 256>>>(img, out, totalCells);
}

// round 11
// speedup vs baseline: 1.0559x; 1.0559x over previous
#include <cuda_runtime.h>

// image [1,128,128,512] f32 NHWC, RoI [N,4] f32 (cx,cy,w,h), POOL=7, STRIDE=16.
#define POOL    7
#define HH      128
#define WW      128
#define CC      512
#define NMAX    1024
#define CPC_MAX 64          // max cells per CTA chunk (smem sizing)

// ---------------------------------------------------------------------------
// Single fused kernel. One wave of persistent CTAs; each CTA owns a
// contiguous chunk of cells.
//   Phase A: threads 0..cpc-1 each compute one cell's bilinear corner
//            offsets + weights straight from the RoI table into smem
//            (math identical to reference: rintf = round-half-even,
//            floor, clip order, int truncation).
//   Phase B: two 128-thread halves sweep the chunk; per cell: 2 broadcast
//            LDS (params, 29cyc), 4 coalesced LDG.128 (corner rows),
//            16 FFMA, 1 streaming STG.128.
// No second kernel, no launch gap, no param round-trip through L2.
// ---------------------------------------------------------------------------
__global__ __launch_bounds__(256, 7)
void roi_pool_fused(const float* __restrict__ img, const float* __restrict__ roi,
                    float* __restrict__ out, int totalCells, int cpc)
{
    __shared__ int4   s_off[CPC_MAX];   // corner offsets, float4 units
    __shared__ float4 s_w  [CPC_MAX];   // bilinear weights

    const int base = blockIdx.x * cpc;
    const int tid  = threadIdx.x;

    if (base >= totalCells) return;

    // ---------------- Phase A: per-cell params into smem ----------------
    if (tid < cpc) {
        int cell = base + tid;
        if (cell < totalCells) {
            int n   = cell / (POOL * POOL);
            int rem = cell - n * (POOL * POOL);
            int py  = rem / POOL;
            int px  = rem - py * POOL;

            const float inv_stride = 1.0f / 16.0f;
            float cx = roi[n * 4 + 0];
            float cy = roi[n * 4 + 1];
            float w  = roi[n * 4 + 2];
            float h  = roi[n * 4 + 3];

            float r  = rintf((cx - 0.5f * w) * inv_stride);   // x start (col)
            float c  = rintf((cy - 0.5f * h) * inv_stride);   // y start (row)
            float wq = fmaxf(rintf(w * inv_stride), 1.0f);
            float hq = fmaxf(rintf(h * inv_stride), 1.0f);

            // y axis (rows, limit HH)
            float gy  = (py + 0.5f) / (float)POOL;
            float sy  = fminf(fmaxf(gy * hq - 0.5f, 0.0f), hq - 1.0f);
            float fy0 = floorf(sy);
            float ly  = sy - fy0;
            float fy1 = fminf(fy0 + 1.0f, hq - 1.0f);
            int iy0 = (int)fminf(fmaxf(c + fy0, 0.0f), (float)(HH - 1));
            int iy1 = (int)fminf(fmaxf(c + fy1, 0.0f), (float)(HH - 1));

            // x axis (cols, limit WW)
            float gx  = (px + 0.5f) / (float)POOL;
            float sx  = fminf(fmaxf(gx * wq - 0.5f, 0.0f), wq - 1.0f);
            float fx0 = floorf(sx);
            float lx  = sx - fx0;
            float fx1 = fminf(fx0 + 1.0f, wq - 1.0f);
            int ix0 = (int)fminf(fmaxf(r + fx0, 0.0f), (float)(WW - 1));
            int ix1 = (int)fminf(fmaxf(r + fx1, 0.0f), (float)(WW - 1));

            s_off[tid] = make_int4((iy0 * WW + ix0) * (CC / 4),
                                   (iy0 * WW + ix1) * (CC / 4),
                                   (iy1 * WW + ix0) * (CC / 4),
                                   (iy1 * WW + ix1) * (CC / 4));
            s_w[tid] = make_float4((1.0f - ly) * (1.0f - lx),
                                   (1.0f - ly) * lx,
                                   ly * (1.0f - lx),
                                   ly * lx);
        }
    }
    __syncthreads();

    // ---------------- Phase B: data sweep ----------------
    const int lane = tid & 127;         // float4 lane within cell
    const int half = tid >> 7;          // which of 2 cells per step

    int nIter = totalCells - base;
    if (nIter > cpc) nIter = cpc;

    const float4* __restrict__ img4 = (const float4*)img;
    float4*       __restrict__ out4 = (float4*)out;

    for (int i = half; i < nIter; i += 2) {
        int4   o = s_off[i];            // broadcast LDS (conflict-free)
        float4 w = s_w[i];

        float4 a = __ldg(img4 + o.x + lane);
        float4 b = __ldg(img4 + o.y + lane);
        float4 c = __ldg(img4 + o.z + lane);
        float4 d = __ldg(img4 + o.w + lane);

        float4 r;
        r.x = w.x * a.x + w.y * b.x + w.z * c.x + w.w * d.x;
        r.y = w.x * a.y + w.y * b.y + w.z * c.y + w.w * d.y;
        r.z = w.x * a.z + w.y * b.z + w.z * c.z + w.w * d.z;
        r.w = w.x * a.w + w.y * b.w + w.z * c.w + w.w * d.w;

        __stcs(out4 + (size_t)(base + i) * (CC / 4) + lane, r);
    }
}

extern "C" void kernel_launch(void* const* d_in, const int* in_sizes, int n_in,
                              void* d_out, int out_size)
{
    const float* img = (const float*)d_in[0];   // [1,128,128,512] f32
    const float* roi = (const float*)d_in[1];   // [N,4] f32
    float*       out = (float*)d_out;           // [1,N,7,7,512] f32

    int N = in_sizes[1] / 4;
    if (N > NMAX) N = NMAX;
    int totalCells = N * POOL * POOL;

    int grid = 148 * 7;                          // exactly one wave at occ=7
    int cpc  = (totalCells + grid - 1) / grid;   // cells per CTA chunk
    if (cpc > CPC_MAX) {                         // safety for huge N
        cpc  = CPC_MAX;
        grid = (totalCells + cpc - 1) / cpc;
    }
    // shrink grid if N is small (no empty CTAs)
    int needed = (totalCells + cpc - 1) / cpc;
    if (grid > needed) grid = needed;

    roi_pool_fused<<<grid, 256>>>(img, roi, out, totalCells, cpc);
}

// round 12
// speedup vs baseline: 1.0645x; 1.0082x over previous
#include <cuda_runtime.h>

// image [1,128,128,512] f32 NHWC, RoI [N,4] f32 (cx,cy,w,h), POOL=7, STRIDE=16.
#define POOL    7
#define HH      128
#define WW      128
#define CC      512
#define NMAX    1024
#define CPC_MAX 96          // max cells per CTA chunk (smem: 96*32B = 3KB)

// ---------------------------------------------------------------------------
// Single fused kernel, one wave of persistent CTAs.
//   Phase A: threads 0..cpc-1 compute their cell's bilinear params from the
//            RoI table into smem (math identical to reference).
//   Phase B: two 128-thread halves sweep the chunk with a SOFTWARE-PIPELINED
//            param fetch: params for iteration i+1 are LDS-prefetched into
//            registers while iteration i's 4 corner LDG.128 are in flight.
//            This is the R9 body (best measured: 29.6us) with smem params
//            instead of L2 params. launch_bounds(256,5) -> ~48 regs so ptxas
//            can actually hold the prefetch + 4 float4 payloads concurrently
//            (the 32-reg cap last round serialized everything: 35.2us).
// ---------------------------------------------------------------------------
__global__ __launch_bounds__(256, 5)
void roi_pool_fused(const float* __restrict__ img, const float* __restrict__ roi,
                    float* __restrict__ out, int totalCells, int cpc)
{
    __shared__ int4   s_off[CPC_MAX];   // corner offsets, float4 units
    __shared__ float4 s_w  [CPC_MAX];   // bilinear weights

    const int base = blockIdx.x * cpc;
    const int tid  = threadIdx.x;

    if (base >= totalCells) return;

    // ---------------- Phase A: per-cell params into smem ----------------
    if (tid < cpc) {
        int cell = base + tid;
        if (cell < totalCells) {
            int n   = cell / (POOL * POOL);
            int rem = cell - n * (POOL * POOL);
            int py  = rem / POOL;
            int px  = rem - py * POOL;

            const float inv_stride = 1.0f / 16.0f;
            float cx = roi[n * 4 + 0];
            float cy = roi[n * 4 + 1];
            float w  = roi[n * 4 + 2];
            float h  = roi[n * 4 + 3];

            float r  = rintf((cx - 0.5f * w) * inv_stride);   // x start (col)
            float c  = rintf((cy - 0.5f * h) * inv_stride);   // y start (row)
            float wq = fmaxf(rintf(w * inv_stride), 1.0f);
            float hq = fmaxf(rintf(h * inv_stride), 1.0f);

            // y axis (rows, limit HH)
            float gy  = (py + 0.5f) / (float)POOL;
            float sy  = fminf(fmaxf(gy * hq - 0.5f, 0.0f), hq - 1.0f);
            float fy0 = floorf(sy);
            float ly  = sy - fy0;
            float fy1 = fminf(fy0 + 1.0f, hq - 1.0f);
            int iy0 = (int)fminf(fmaxf(c + fy0, 0.0f), (float)(HH - 1));
            int iy1 = (int)fminf(fmaxf(c + fy1, 0.0f), (float)(HH - 1));

            // x axis (cols, limit WW)
            float gx  = (px + 0.5f) / (float)POOL;
            float sx  = fminf(fmaxf(gx * wq - 0.5f, 0.0f), wq - 1.0f);
            float fx0 = floorf(sx);
            float lx  = sx - fx0;
            float fx1 = fminf(fx0 + 1.0f, wq - 1.0f);
            int ix0 = (int)fminf(fmaxf(r + fx0, 0.0f), (float)(WW - 1));
            int ix1 = (int)fminf(fmaxf(r + fx1, 0.0f), (float)(WW - 1));

            s_off[tid] = make_int4((iy0 * WW + ix0) * (CC / 4),
                                   (iy0 * WW + ix1) * (CC / 4),
                                   (iy1 * WW + ix0) * (CC / 4),
                                   (iy1 * WW + ix1) * (CC / 4));
            s_w[tid] = make_float4((1.0f - ly) * (1.0f - lx),
                                   (1.0f - ly) * lx,
                                   ly * (1.0f - lx),
                                   ly * lx);
        }
    }
    __syncthreads();

    // ---------------- Phase B: pipelined data sweep ----------------
    const int lane = tid & 127;         // float4 lane within cell
    const int half = tid >> 7;          // which of 2 interleaved cells

    int nIter = totalCells - base;
    if (nIter > cpc) nIter = cpc;

    const float4* __restrict__ img4 = (const float4*)img;
    float4*       __restrict__ out4 = (float4*)out;

    int i = half;
    if (i >= nIter) return;

    // Prime: params for first owned cell.
    int4   o = s_off[i];
    float4 w = s_w[i];

    while (true) {
        int nx = i + 2;

        // Prefetch next params (LDS, independent of this iteration's data).
        int4   o_n = o;
        float4 w_n = w;
        if (nx < nIter) {
            o_n = s_off[nx];
            w_n = s_w[nx];
        }

        // 4 independent corner loads for this cell.
        float4 a = __ldg(img4 + o.x + lane);
        float4 b = __ldg(img4 + o.y + lane);
        float4 c = __ldg(img4 + o.z + lane);
        float4 d = __ldg(img4 + o.w + lane);

        float4 r;
        r.x = w.x * a.x + w.y * b.x + w.z * c.x + w.w * d.x;
        r.y = w.x * a.y + w.y * b.y + w.z * c.y + w.w * d.y;
        r.z = w.x * a.z + w.y * b.z + w.z * c.z + w.w * d.z;
        r.w = w.x * a.w + w.y * b.w + w.z * c.w + w.w * d.w;

        __stcs(out4 + (size_t)(base + i) * (CC / 4) + lane, r);

        if (nx >= nIter) break;
        i = nx;
        o = o_n;
        w = w_n;
    }
}

extern "C" void kernel_launch(void* const* d_in, const int* in_sizes, int n_in,
                              void* d_out, int out_size)
{
    const float* img = (const float*)d_in[0];   // [1,128,128,512] f32
    const float* roi = (const float*)d_in[1];   // [N,4] f32
    float*       out = (float*)d_out;           // [1,N,7,7,512] f32

    int N = in_sizes[1] / 4;
    if (N > NMAX) N = NMAX;
    int totalCells = N * POOL * POOL;

    int wave = 148 * 5;                          // one wave at occ=5
    int cpc  = (totalCells + wave - 1) / wave;   // cells per CTA chunk
    if (cpc > CPC_MAX) cpc = CPC_MAX;
    int grid = (totalCells + cpc - 1) / cpc;

    roi_pool_fused<<<grid, 256>>>(img, roi, out, totalCells, cpc);
}

// round 13
// speedup vs baseline: 1.0857x; 1.0199x over previous
#include <cuda_runtime.h>

// image [1,128,128,512] f32 NHWC, RoI [N,4] f32 (cx,cy,w,h), POOL=7, STRIDE=16.
#define POOL    7
#define HH      128
#define WW      128
#define CC      512
#define NMAX    1024
#define CPC_MAX 96          // max cells per CTA chunk (smem: 96*32B = 3KB)

// ---------------------------------------------------------------------------
// Single fused kernel, one wave of persistent CTAs.
//   Phase A: threads 0..cpc-1 compute their cell's bilinear params from the
//            RoI table into smem (math identical to reference).
//   Phase B: ROTATING REGISTER DOUBLE-BUFFER. Each iteration issues the 4
//            corner LDG.128 for the NEXT cell into buffer B, then blends and
//            stores the CURRENT cell from buffer A (loaded a full iteration
//            ago). Consumption never waits on just-issued loads: the ~250cyc
//            L2 latency is covered by one whole iteration of multi-warp
//            issue. This is the piece every previous ~30us variant lacked —
//            they issued and consumed the same batch within one iteration.
//            launch_bounds(256,4) -> 64-reg cap for 2x16 payload regs.
// ---------------------------------------------------------------------------
__global__ __launch_bounds__(256, 4)
void roi_pool_fused(const float* __restrict__ img, const float* __restrict__ roi,
                    float* __restrict__ out, int totalCells, int cpc)
{
    __shared__ int4   s_off[CPC_MAX];   // corner offsets, float4 units
    __shared__ float4 s_w  [CPC_MAX];   // bilinear weights

    const int base = blockIdx.x * cpc;
    const int tid  = threadIdx.x;

    if (base >= totalCells) return;

    // ---------------- Phase A: per-cell params into smem ----------------
    if (tid < cpc) {
        int cell = base + tid;
        if (cell < totalCells) {
            int n   = cell / (POOL * POOL);
            int rem = cell - n * (POOL * POOL);
            int py  = rem / POOL;
            int px  = rem - py * POOL;

            const float inv_stride = 1.0f / 16.0f;
            float cx = roi[n * 4 + 0];
            float cy = roi[n * 4 + 1];
            float w  = roi[n * 4 + 2];
            float h  = roi[n * 4 + 3];

            float r  = rintf((cx - 0.5f * w) * inv_stride);   // x start (col)
            float c  = rintf((cy - 0.5f * h) * inv_stride);   // y start (row)
            float wq = fmaxf(rintf(w * inv_stride), 1.0f);
            float hq = fmaxf(rintf(h * inv_stride), 1.0f);

            // y axis (rows, limit HH)
            float gy  = (py + 0.5f) / (float)POOL;
            float sy  = fminf(fmaxf(gy * hq - 0.5f, 0.0f), hq - 1.0f);
            float fy0 = floorf(sy);
            float ly  = sy - fy0;
            float fy1 = fminf(fy0 + 1.0f, hq - 1.0f);
            int iy0 = (int)fminf(fmaxf(c + fy0, 0.0f), (float)(HH - 1));
            int iy1 = (int)fminf(fmaxf(c + fy1, 0.0f), (float)(HH - 1));

            // x axis (cols, limit WW)
            float gx  = (px + 0.5f) / (float)POOL;
            float sx  = fminf(fmaxf(gx * wq - 0.5f, 0.0f), wq - 1.0f);
            float fx0 = floorf(sx);
            float lx  = sx - fx0;
            float fx1 = fminf(fx0 + 1.0f, wq - 1.0f);
            int ix0 = (int)fminf(fmaxf(r + fx0, 0.0f), (float)(WW - 1));
            int ix1 = (int)fminf(fmaxf(r + fx1, 0.0f), (float)(WW - 1));

            s_off[tid] = make_int4((iy0 * WW + ix0) * (CC / 4),
                                   (iy0 * WW + ix1) * (CC / 4),
                                   (iy1 * WW + ix0) * (CC / 4),
                                   (iy1 * WW + ix1) * (CC / 4));
            s_w[tid] = make_float4((1.0f - ly) * (1.0f - lx),
                                   (1.0f - ly) * lx,
                                   ly * (1.0f - lx),
                                   ly * lx);
        }
    }
    __syncthreads();

    // ---------------- Phase B: double-buffered data sweep ----------------
    const int lane = tid & 127;         // float4 lane within cell
    const int half = tid >> 7;          // which of 2 interleaved cells

    int nIter = totalCells - base;
    if (nIter > cpc) nIter = cpc;

    const float4* __restrict__ img4 = (const float4*)img;
    float4*       __restrict__ out4 = (float4*)out;

    int i = half;
    if (i >= nIter) return;

    // Prime: params + data loads for first owned cell.
    int4   o0 = s_off[i];
    float4 w0 = s_w[i];
    float4 a0 = __ldg(img4 + o0.x + lane);
    float4 b0 = __ldg(img4 + o0.y + lane);
    float4 c0 = __ldg(img4 + o0.z + lane);
    float4 d0 = __ldg(img4 + o0.w + lane);

    while (true) {
        int  nx   = i + 2;
        bool more = nx < nIter;

        // Issue NEXT cell's loads first (buffer B) — consumed next iteration.
        int4   o1;
        float4 w1;
        float4 a1, b1, c1, d1;
        if (more) {
            o1 = s_off[nx];
            w1 = s_w[nx];
            a1 = __ldg(img4 + o1.x + lane);
            b1 = __ldg(img4 + o1.y + lane);
            c1 = __ldg(img4 + o1.z + lane);
            d1 = __ldg(img4 + o1.w + lane);
        }

        // Consume CURRENT cell (loads issued one full iteration ago).
        float4 r;
        r.x = w0.x * a0.x + w0.y * b0.x + w0.z * c0.x + w0.w * d0.x;
        r.y = w0.x * a0.y + w0.y * b0.y + w0.z * c0.y + w0.w * d0.y;
        r.z = w0.x * a0.z + w0.y * b0.z + w0.z * c0.z + w0.w * d0.z;
        r.w = w0.x * a0.w + w0.y * b0.w + w0.z * c0.w + w0.w * d0.w;

        __stcs(out4 + (size_t)(base + i) * (CC / 4) + lane, r);

        if (!more) break;
        i = nx;
        o0 = o1; w0 = w1;
        a0 = a1; b0 = b1; c0 = c1; d0 = d1;
    }
}

extern "C" void kernel_launch(void* const* d_in, const int* in_sizes, int n_in,
                              void* d_out, int out_size)
{
    const float* img = (const float*)d_in[0];   // [1,128,128,512] f32
    const float* roi = (const float*)d_in[1];   // [N,4] f32
    float*       out = (float*)d_out;           // [1,N,7,7,512] f32

    int N = in_sizes[1] / 4;
    if (N > NMAX) N = NMAX;
    int totalCells = N * POOL * POOL;

    int wave = 148 * 4;                          // one wave at occ=4
    int cpc  = (totalCells + wave - 1) / wave;   // cells per CTA chunk
    if (cpc > CPC_MAX) cpc = CPC_MAX;
    int grid = (totalCells + cpc - 1) / cpc;

    roi_pool_fused<<<grid, 256>>>(img, roi, out, totalCells, cpc);
}